// round 4
// baseline (speedup 1.0000x reference)
#include <cuda_runtime.h>
#include <cstdint>

// ---------------------------------------------------------------------------
// CTMCell: B=256, OBS=256, DIN=512, D=1024, M=32, HID=16, NSY=64, ITERS=4
// Outputs: st [B,D,M], at [B,D,M], synch [B,2080]  (concatenated, fp32)
// ---------------------------------------------------------------------------

#define B_   256
#define OBS_ 256
#define DIN_ 512
#define D_   1024
#define M_   32
#define NSY_ 64
#define SYNCH_ 2080
#define BD_ (B_ * D_)   // 262144

// ------------------------- scratch (static device) -------------------------
__device__ float g_z[B_ * 2048];      // GEMM output scratch
__device__ float g_c1[B_ * 2048];     // f @ syn_w1[0:512] + syn_b1  (loop invariant)
__device__ float g_f1[B_ * DIN_];
__device__ float g_f[B_ * DIN_];
__device__ float g_h1[B_ * D_];       // syn stage-1 activations, [B][D]
__device__ float g_h[4 * BD_];        // new st columns, [t][d][b]
__device__ float g_x[4 * BD_];        // new at columns, [t][d][b]
__device__ float g_last0[BD_];        // initial "last" = at0[:, :, 31], [d][b]
__device__ float g_wt1[D_ * 32 * 32]; // nlm1_w transposed -> [d][m][h]
__device__ float g_wt2[D_ * 32];      // nlm2_w transposed -> [d][h*2+k]
__device__ unsigned char g_dones[B_]; // canonical dones (0/1)

// ----------------------- dones dtype detect + decode -----------------------
// The reference 'dones' is a JAX bool array; the harness may have stored it as
// bool/uint8 (1B), int32 (4B, LE) or float32 (4B). Detect from the first 256
// bytes (valid under all three layouts), then decode accordingly.
__global__ __launch_bounds__(256) void dones_prep_k(const unsigned char* __restrict__ raw)
{
    __shared__ int f_anom;   // any byte not in {0,1}  -> float32
    __shared__ int f_mis;    // any byte==1 at p%4!=0  -> uint8/bool
    const int b = threadIdx.x;
    if (b == 0) { f_anom = 0; f_mis = 0; }
    __syncthreads();
    unsigned char v = raw[b];
    if (v > 1) atomicOr(&f_anom, 1);
    if ((b & 3) != 0 && v == 1) atomicOr(&f_mis, 1);
    __syncthreads();
    unsigned char o;
    if (f_anom) {
        // float32: true iff exponent byte nonzero (1.0f -> 0x3F at byte 3)
        o = (raw[b * 4 + 3] != 0) ? 1 : 0;
    } else if (f_mis) {
        o = v;                        // uint8/bool layout
    } else {
        o = raw[b * 4];               // int32 little-endian LSB (0/1)
    }
    g_dones[b] = o;
}

// ------------------------------ tiled GEMM ---------------------------------
// C[M,N] = A[M,K] * B[K,N] (+bias[N]) (+Cinit[M,N])
// AKM=true: A stored K-major, A[k*lda + m].
#define GBM 64
#define GBN 64
#define GBK 16

template <bool AKM>
__global__ __launch_bounds__(256) void gemm_k(
    const float* __restrict__ A, int lda,
    const float* __restrict__ Bm, int ldb,
    float* __restrict__ C, int ldc, int K,
    const float* __restrict__ bias, const float* __restrict__ Cinit)
{
    __shared__ __align__(16) float As[GBK][GBM + 4];
    __shared__ __align__(16) float Bs[GBK][GBN + 4];
    const int tid = threadIdx.x;
    const int m0 = blockIdx.y * GBM;
    const int n0 = blockIdx.x * GBN;
    const int tx = tid & 15, ty = tid >> 4;

    float acc[4][4];
#pragma unroll
    for (int i = 0; i < 4; i++)
#pragma unroll
        for (int j = 0; j < 4; j++) acc[i][j] = 0.f;

    for (int k0 = 0; k0 < K; k0 += GBK) {
        if (AKM) {
            const int lk = tid >> 4;            // 0..15
            const int lm = (tid & 15) * 4;      // 0..60
            float4 v = *(const float4*)(A + (size_t)(k0 + lk) * lda + m0 + lm);
            *(float4*)&As[lk][lm] = v;
        } else {
            const int lm = tid >> 2;            // 0..63
            const int lk = (tid & 3) * 4;       // 0..12
            float4 v = *(const float4*)(A + (size_t)(m0 + lm) * lda + k0 + lk);
            As[lk + 0][lm] = v.x; As[lk + 1][lm] = v.y;
            As[lk + 2][lm] = v.z; As[lk + 3][lm] = v.w;
        }
        {
            const int lk = tid >> 4;
            const int ln = (tid & 15) * 4;
            float4 v = *(const float4*)(Bm + (size_t)(k0 + lk) * ldb + n0 + ln);
            *(float4*)&Bs[lk][ln] = v;
        }
        __syncthreads();
#pragma unroll
        for (int kk = 0; kk < GBK; kk++) {
            float4 a = *(const float4*)&As[kk][ty * 4];
            float4 b = *(const float4*)&Bs[kk][tx * 4];
            float av[4] = {a.x, a.y, a.z, a.w};
            float bv[4] = {b.x, b.y, b.z, b.w};
#pragma unroll
            for (int i = 0; i < 4; i++)
#pragma unroll
                for (int j = 0; j < 4; j++) acc[i][j] += av[i] * bv[j];
        }
        __syncthreads();
    }

#pragma unroll
    for (int i = 0; i < 4; i++) {
        const int row = m0 + ty * 4 + i;
        float add[4] = {0.f, 0.f, 0.f, 0.f};
        if (bias) {
            float4 bb = *(const float4*)(bias + n0 + tx * 4);
            add[0] = bb.x; add[1] = bb.y; add[2] = bb.z; add[3] = bb.w;
        }
        if (Cinit) {
            float4 ci = *(const float4*)(Cinit + (size_t)row * ldc + n0 + tx * 4);
            add[0] += ci.x; add[1] += ci.y; add[2] += ci.z; add[3] += ci.w;
        }
        float4 o;
        o.x = acc[i][0] + add[0]; o.y = acc[i][1] + add[1];
        o.z = acc[i][2] + add[2]; o.w = acc[i][3] + add[3];
        *(float4*)(C + (size_t)row * ldc + n0 + tx * 4) = o;
    }
}

// --------------------------- fused GLU + LayerNorm -------------------------
// Z [B][2W] -> out [B][W] (or transposed [W][B] when TRANS)
template <int W, bool TRANS>
__global__ __launch_bounds__(256) void gluln_k(
    const float* __restrict__ Z, const float* __restrict__ sc,
    const float* __restrict__ bi, float* __restrict__ out)
{
    __shared__ float g[W];
    __shared__ float red[16];
    const int b = blockIdx.x, tid = threadIdx.x;
    const float* z = Z + (size_t)b * (2 * W);
    float ls = 0.f, lq = 0.f;
    for (int i = tid; i < W; i += 256) {
        float a = z[i];
        float xx = z[i + W];
        float gv = a / (1.f + __expf(-xx));
        g[i] = gv; ls += gv; lq += gv * gv;
    }
#pragma unroll
    for (int o = 16; o; o >>= 1) {
        ls += __shfl_xor_sync(0xffffffffu, ls, o);
        lq += __shfl_xor_sync(0xffffffffu, lq, o);
    }
    if ((tid & 31) == 0) { red[tid >> 5] = ls; red[8 + (tid >> 5)] = lq; }
    __syncthreads();
    if (tid == 0) {
        float s = 0.f, q = 0.f;
        for (int w = 0; w < 8; w++) { s += red[w]; q += red[8 + w]; }
        red[0] = s; red[8] = q;
    }
    __syncthreads();
    const float mean = red[0] * (1.0f / W);
    const float var = red[8] * (1.0f / W) - mean * mean;
    const float rstd = rsqrtf(var + 1e-6f);
    for (int i = tid; i < W; i += 256) {
        float o = (g[i] - mean) * rstd * sc[i] + bi[i];
        if (TRANS) out[(size_t)i * B_ + b] = o;
        else       out[(size_t)b * W + i] = o;
    }
}

// --------------------------- small helper kernels --------------------------
__global__ __launch_bounds__(256) void last0_k(
    const float* __restrict__ at_tr, const float* __restrict__ start_at)
{
    const int d = blockIdx.x, b = threadIdx.x;
    const bool dn = g_dones[b] != 0;
    g_last0[(size_t)d * B_ + b] =
        dn ? __ldg(start_at + d * M_ + (M_ - 1))
           : __ldg(at_tr + ((size_t)b * D_ + d) * M_ + (M_ - 1));
}

// in[R][C] -> out[C][R]
__global__ __launch_bounds__(256) void transpose_k(
    const float* __restrict__ in, float* __restrict__ out, int R, int C)
{
    const int o = blockIdx.x * 256 + threadIdx.x;
    if (o >= R * C) return;
    const int c = o / R, r = o - c * R;
    out[o] = __ldg(in + (size_t)r * C + c);
}

// ------------------------------ NLM kernel ---------------------------------
// block = d, thread = b. Computes x_t[b,d] from the rolling st window.
template <int IT>
__global__ __launch_bounds__(256) void nlm_k(
    const float* __restrict__ st_tr, const float* __restrict__ start_st,
    const float* __restrict__ b1, const float* __restrict__ b2,
    const float* __restrict__ T1p, const float* __restrict__ T2p)
{
    const int d = blockIdx.x, b = threadIdx.x;
    __shared__ __align__(16) float w1s[32][36];
    __shared__ float w2s[32];
    __shared__ float b1s[32];
    __shared__ float sts[32];
    __shared__ float b2s[2];

    const float* w1g = g_wt1 + (size_t)d * 1024;
    for (int i = b; i < 1024; i += 256) w1s[i >> 5][i & 31] = w1g[i];
    if (b < 32) {
        w2s[b] = g_wt2[d * 32 + b];
        b1s[b] = b1[d * 32 + b];
        sts[b] = start_st[d * 32 + b];
    }
    if (b < 2) b2s[b] = b2[d * 2 + b];
    __syncthreads();

    const float invT1 = 1.f / T1p[0], invT2 = 1.f / T2p[0];
    const bool dn = g_dones[b] != 0;
    const float* strow = st_tr + ((size_t)b * D_ + d) * M_;

    float sv[32];
#pragma unroll
    for (int m = 0; m < 32; m++) {
        if (m < 31 - IT) {
            const int mm = m + IT + 1;
            sv[m] = dn ? sts[mm] : __ldg(strow + mm);
        } else {
            sv[m] = g_h[(size_t)(m - (31 - IT)) * BD_ + (size_t)d * B_ + b];
        }
    }

    float y[32];
#pragma unroll
    for (int h = 0; h < 32; h++) y[h] = b1s[h];
#pragma unroll
    for (int m = 0; m < 32; m++) {
        const float s = sv[m];
#pragma unroll
        for (int h4 = 0; h4 < 8; h4++) {
            float4 w = *(const float4*)&w1s[m][h4 * 4];
            y[h4 * 4 + 0] += s * w.x; y[h4 * 4 + 1] += s * w.y;
            y[h4 * 4 + 2] += s * w.z; y[h4 * 4 + 3] += s * w.w;
        }
    }
    float gg[16];
#pragma unroll
    for (int h = 0; h < 16; h++) {
        const float a = y[h] * invT1;
        const float bb = y[h + 16] * invT1;
        gg[h] = a / (1.f + __expf(-bb));
    }
    float z0 = b2s[0], z1 = b2s[1];
#pragma unroll
    for (int h = 0; h < 16; h++) {
        z0 += gg[h] * w2s[h * 2];
        z1 += gg[h] * w2s[h * 2 + 1];
    }
    z0 *= invT2; z1 *= invT2;
    const float xo = z0 / (1.f + __expf(-z1));
    g_x[(size_t)IT * BD_ + (size_t)d * B_ + b] = xo;
}

// ------------------------------ final outputs ------------------------------
__global__ __launch_bounds__(256) void output_k(
    const float* __restrict__ st_tr, const float* __restrict__ at_tr,
    const float* __restrict__ start_st, const float* __restrict__ start_at,
    float* __restrict__ out)
{
    const int d = blockIdx.x, b = threadIdx.x;
    __shared__ float sst[32], sat[32];
    if (b < 32) { sst[b] = start_st[d * M_ + b]; sat[b] = start_at[d * M_ + b]; }
    __syncthreads();
    const bool dn = g_dones[b] != 0;
    const size_t base = ((size_t)b * D_ + d) * M_;

    float v[32];
#pragma unroll
    for (int m = 0; m < 28; m++) v[m] = dn ? sst[m + 4] : __ldg(st_tr + base + m + 4);
#pragma unroll
    for (int j = 0; j < 4; j++) v[28 + j] = g_h[(size_t)j * BD_ + (size_t)d * B_ + b];
    float* o = out + base;
#pragma unroll
    for (int q = 0; q < 8; q++)
        *(float4*)(o + q * 4) = make_float4(v[q*4], v[q*4+1], v[q*4+2], v[q*4+3]);

#pragma unroll
    for (int m = 0; m < 28; m++) v[m] = dn ? sat[m + 4] : __ldg(at_tr + base + m + 4);
#pragma unroll
    for (int j = 0; j < 4; j++) v[28 + j] = g_x[(size_t)j * BD_ + (size_t)d * B_ + b];
    o = out + (size_t)B_ * D_ * M_ + base;
#pragma unroll
    for (int q = 0; q < 8; q++)
        *(float4*)(o + q * 4) = make_float4(v[q*4], v[q*4+1], v[q*4+2], v[q*4+3]);
}

__global__ __launch_bounds__(256) void synch_k(
    const float* __restrict__ at_tr, const float* __restrict__ start_at,
    const float* __restrict__ dp, float* __restrict__ out)
{
    const int b = blockIdx.x, tid = threadIdx.x;
    __shared__ float S[32][65];
    const bool dn = g_dones[b] != 0;
    for (int idx = tid; idx < 32 * 64; idx += 256) {
        const int m = idx >> 6, j = idx & 63;
        const int d = D_ - NSY_ + j;
        float v;
        if (m < 28)
            v = dn ? __ldg(start_at + d * M_ + m + 4)
                   : __ldg(at_tr + ((size_t)b * D_ + d) * M_ + m + 4);
        else
            v = g_x[(size_t)(m - 28) * BD_ + (size_t)d * B_ + b];
        S[m][j] = v;
    }
    __syncthreads();
    for (int s = tid; s < SYNCH_; s += 256) {
        int i = (int)((129.0f - sqrtf(16641.0f - 8.0f * (float)s)) * 0.5f);
        if (i < 0) i = 0; if (i > 63) i = 63;
        while (i > 0 && i * (129 - i) / 2 > s) i--;
        while ((i + 1) * (129 - (i + 1)) / 2 <= s) i++;
        const int j = i + (s - i * (129 - i) / 2);
        const float c = fminf(fmaxf(dp[s], 0.f), 4.f);
        const float r = __expf(-c);
        float acc = 0.f, den = 0.f, p = 1.f;
#pragma unroll
        for (int m = 31; m >= 0; m--) {
            acc += p * S[m][i] * S[m][j];
            den += p;
            p *= r;
        }
        out[(size_t)b * SYNCH_ + s] = acc * rsqrtf(den);
    }
}

// ------------------------------- host driver -------------------------------
extern "C" void kernel_launch(void* const* d_in, const int* in_sizes, int n_in,
                              void* d_out, int out_size)
{
    const float* obs       = (const float*)d_in[0];
    const unsigned char* dones_raw = (const unsigned char*)d_in[1];
    const float* st_tr     = (const float*)d_in[3];
    const float* at_tr     = (const float*)d_in[4];
    const float* start_st  = (const float*)d_in[5];
    const float* start_at  = (const float*)d_in[6];
    const float* bb_w1     = (const float*)d_in[7];
    const float* bb_b1     = (const float*)d_in[8];
    const float* bb_ln1_s  = (const float*)d_in[9];
    const float* bb_ln1_b  = (const float*)d_in[10];
    const float* bb_w2     = (const float*)d_in[11];
    const float* bb_b2     = (const float*)d_in[12];
    const float* bb_ln2_s  = (const float*)d_in[13];
    const float* bb_ln2_b  = (const float*)d_in[14];
    const float* syn_w1    = (const float*)d_in[15];
    const float* syn_b1    = (const float*)d_in[16];
    const float* syn_ln1_s = (const float*)d_in[17];
    const float* syn_ln1_b = (const float*)d_in[18];
    const float* syn_w2    = (const float*)d_in[19];
    const float* syn_b2    = (const float*)d_in[20];
    const float* syn_ln2_s = (const float*)d_in[21];
    const float* syn_ln2_b = (const float*)d_in[22];
    const float* nlm1_w    = (const float*)d_in[23];
    const float* nlm1_b    = (const float*)d_in[24];
    const float* nlm1_T    = (const float*)d_in[25];
    const float* nlm2_w    = (const float*)d_in[26];
    const float* nlm2_b    = (const float*)d_in[27];
    const float* nlm2_T    = (const float*)d_in[28];
    const float* dp        = (const float*)d_in[29];
    float* out = (float*)d_out;

    // resolve all scratch addresses once, up-front (capture-safe: no stream work)
    float *z, *c1, *f1, *f, *h1, *x, *h, *last0, *wt1, *wt2;
    cudaGetSymbolAddress((void**)&z,     g_z);
    cudaGetSymbolAddress((void**)&c1,    g_c1);
    cudaGetSymbolAddress((void**)&f1,    g_f1);
    cudaGetSymbolAddress((void**)&f,     g_f);
    cudaGetSymbolAddress((void**)&h1,    g_h1);
    cudaGetSymbolAddress((void**)&x,     g_x);
    cudaGetSymbolAddress((void**)&h,     g_h);
    cudaGetSymbolAddress((void**)&last0, g_last0);
    cudaGetSymbolAddress((void**)&wt1,   g_wt1);
    cudaGetSymbolAddress((void**)&wt2,   g_wt2);

    const dim3 thr(256);

    // canonicalize dones (dtype-robust)
    dones_prep_k<<<1, thr>>>(dones_raw);

    // one-time transposes of NLM weights (-> [d][...] layouts)
    transpose_k<<<(D_ * 1024 + 255) / 256, thr>>>(nlm1_w, wt1, 1024, D_);
    transpose_k<<<(D_ * 32 + 255) / 256, thr>>>(nlm2_w, wt2, 32, D_);

    // backbone: f = ln(glu(ln(glu(obs@W1+b1))@W2+b2))
    gemm_k<false><<<dim3(1024 / GBN, B_ / GBM), thr>>>(obs, OBS_, bb_w1, 1024, z, 1024, OBS_, bb_b1, nullptr);
    gluln_k<512, false><<<B_, thr>>>(z, bb_ln1_s, bb_ln1_b, f1);
    gemm_k<false><<<dim3(1024 / GBN, B_ / GBM), thr>>>(f1, DIN_, bb_w2, 1024, z, 1024, DIN_, bb_b2, nullptr);
    gluln_k<512, false><<<B_, thr>>>(z, bb_ln2_s, bb_ln2_b, f);

    // loop-invariant part of the synapse GEMM: c1 = f @ syn_w1[0:512] + syn_b1
    gemm_k<false><<<dim3(2048 / GBN, B_ / GBM), thr>>>(f, DIN_, syn_w1, 2048, c1, 2048, DIN_, syn_b1, nullptr);

    last0_k<<<D_, thr>>>(at_tr, start_at);

    for (int t = 0; t < 4; t++) {
        const float* lastA = (t == 0) ? last0 : (x + (size_t)(t - 1) * BD_);
        // z = c1 + last @ syn_w1[512:1536]   (last is K-major [d][b])
        gemm_k<true><<<dim3(2048 / GBN, B_ / GBM), thr>>>(
            lastA, B_, syn_w1 + (size_t)DIN_ * 2048, 2048, z, 2048, D_, nullptr, c1);
        gluln_k<1024, false><<<B_, thr>>>(z, syn_ln1_s, syn_ln1_b, h1);
        // z = h1 @ syn_w2 + syn_b2
        gemm_k<false><<<dim3(2048 / GBN, B_ / GBM), thr>>>(
            h1, D_, syn_w2, 2048, z, 2048, D_, syn_b2, nullptr);
        // h_t (transposed [d][b]) = ln(glu(z))
        gluln_k<1024, true><<<B_, thr>>>(z, syn_ln2_s, syn_ln2_b, h + (size_t)t * BD_);
        // x_t = NLM(rolling st window)
        switch (t) {
            case 0: nlm_k<0><<<D_, thr>>>(st_tr, start_st, nlm1_b, nlm2_b, nlm1_T, nlm2_T); break;
            case 1: nlm_k<1><<<D_, thr>>>(st_tr, start_st, nlm1_b, nlm2_b, nlm1_T, nlm2_T); break;
            case 2: nlm_k<2><<<D_, thr>>>(st_tr, start_st, nlm1_b, nlm2_b, nlm1_T, nlm2_T); break;
            case 3: nlm_k<3><<<D_, thr>>>(st_tr, start_st, nlm1_b, nlm2_b, nlm1_T, nlm2_T); break;
        }
    }

    output_k<<<D_, thr>>>(st_tr, at_tr, start_st, start_at, out);
    synch_k<<<B_, thr>>>(at_tr, start_at, dp, out + (size_t)2 * B_ * D_ * M_);
}

// round 8
// speedup vs baseline: 1.5917x; 1.5917x over previous
#include <cuda_runtime.h>
#include <cstdint>

// ---------------------------------------------------------------------------
// CTMCell: B=256, OBS=256, DIN=512, D=1024, M=32, HID=16, NSY=64, ITERS=4
// Outputs: st [B,D,M], at [B,D,M], synch [B,2080]  (fp32, concatenated)
// GEMMs: mma.sync m16n8k8 tf32 (operands pre-rounded rna at producers).
// ---------------------------------------------------------------------------

#define B_   256
#define OBS_ 256
#define DIN_ 512
#define D_   1024
#define M_   32
#define NSY_ 64
#define SYNCH_ 2080
#define BD_ (B_ * D_)   // 262144

// ------------------------- scratch (static device) -------------------------
__device__ float g_z[B_ * 2048];
__device__ float g_c1[B_ * 2048];
__device__ float g_f1[B_ * DIN_];
__device__ float g_f[B_ * DIN_];
__device__ float g_h1[B_ * D_];
__device__ float g_h[4 * BD_];        // new st columns, [t][d][b]  (fp32)
__device__ float g_x[4 * BD_];        // new at columns, [t][d][b]  (fp32)
__device__ float g_lastT[B_ * D_];    // "last" activations, [b][d], tf32-rounded
__device__ float g_obsr[B_ * OBS_];   // obs, tf32-rounded
__device__ float g_wt1[D_ * 32 * 32];
__device__ float g_wt2[D_ * 32];
__device__ unsigned char g_dones[B_];
// transposed weights -> [n][k], k contiguous, tf32-rounded
__device__ float g_WTbb1[1024 * 256];
__device__ float g_WTbb2[1024 * 512];
__device__ float g_WT1a[2048 * 512];
__device__ float g_WT1b[2048 * 1024];
__device__ float g_WT2 [2048 * 1024];

// ------------------------------ helpers ------------------------------------
__device__ __forceinline__ float tf32r(float x) {
    uint32_t u;
    asm("cvt.rna.tf32.f32 %0, %1;" : "=r"(u) : "f"(x));
    return __uint_as_float(u);
}
__device__ __forceinline__ uint32_t smem_u32(const void* p) {
    uint32_t a;
    asm("{ .reg .u64 t; cvta.to.shared.u64 t, %1; cvt.u32.u64 %0, t; }"
        : "=r"(a) : "l"(p));
    return a;
}
#define CP_ASYNC16(dst, src) \
    asm volatile("cp.async.cg.shared.global [%0], [%1], 16;" \
                 :: "r"(dst), "l"(src) : "memory")
#define CP_COMMIT() asm volatile("cp.async.commit_group;" ::: "memory")

__device__ __forceinline__ void mma_tf32(float* c, const uint32_t* a, const uint32_t* b) {
    asm volatile(
        "mma.sync.aligned.m16n8k8.row.col.f32.tf32.tf32.f32 "
        "{%0,%1,%2,%3}, {%4,%5,%6,%7}, {%8,%9}, {%0,%1,%2,%3};"
        : "+f"(c[0]), "+f"(c[1]), "+f"(c[2]), "+f"(c[3])
        : "r"(a[0]), "r"(a[1]), "r"(a[2]), "r"(a[3]), "r"(b[0]), "r"(b[1]));
}

// ----------------------- tensor-core GEMM (tf32 mma.sync) ------------------
// C[M,N] = A[M,K](row-major) * Bt[N,K](row-major)^T (+bias[N]) (+Cinit[M,N])
// CTA tile 64x64, 8 warps (2m x 4n), warp tile 32x16, KC=32, double buffer.
#define LDP 36   // smem row pitch (floats): (4g+t4)%32 bijective -> conflict-free

__global__ __launch_bounds__(256) void gemm_mma(
    const float* __restrict__ A, const float* __restrict__ Bt,
    const float* __restrict__ bias, const float* __restrict__ Cinit,
    float* __restrict__ C, int K, int ldc)
{
    __shared__ __align__(16) float As[2][64 * LDP];
    __shared__ __align__(16) float Bs[2][64 * LDP];
    const int tid = threadIdx.x;
    const int m0 = blockIdx.y * 64, n0 = blockIdx.x * 64;
    const int w = tid >> 5, lane = tid & 31;
    const int wm = (w >> 2) * 32, wn = (w & 3) * 16;
    const int g = lane >> 2, t4 = lane & 3;
    const int NC = K / 32;

    float acc[2][2][4];
#pragma unroll
    for (int mi = 0; mi < 2; mi++)
#pragma unroll
        for (int ni = 0; ni < 2; ni++)
#pragma unroll
            for (int q = 0; q < 4; q++) acc[mi][ni][q] = 0.f;

    const uint32_t sa0 = smem_u32(&As[0][0]);
    const uint32_t sb0 = smem_u32(&Bs[0][0]);

    // load chunk c into stage s
    auto load_chunk = [&](int s, int c) {
        const int k0 = c * 32;
#pragma unroll
        for (int i = 0; i < 2; i++) {
            const int gi = tid + i * 256;          // 0..511
            const int row = gi >> 3, g8 = gi & 7;  // row 0..63, 16B granule 0..7
            const uint32_t off = (uint32_t)s * (64 * LDP * 4) + (uint32_t)row * (LDP * 4) + (uint32_t)g8 * 16;
            CP_ASYNC16(sa0 + off, A  + (size_t)(m0 + row) * K + k0 + g8 * 4);
            CP_ASYNC16(sb0 + off, Bt + (size_t)(n0 + row) * K + k0 + g8 * 4);
        }
        CP_COMMIT();
    };

    load_chunk(0, 0);
    load_chunk(1, 1);

    for (int c = 0; c < NC; c++) {
        const int s = c & 1;
        if (c + 2 <= NC) asm volatile("cp.async.wait_group 1;" ::: "memory");
        else             asm volatile("cp.async.wait_group 0;" ::: "memory");
        __syncthreads();

        const float* as = As[s];
        const float* bs = Bs[s];
#pragma unroll
        for (int kk = 0; kk < 4; kk++) {
            const int kb = kk * 8;
            uint32_t a[2][4], b[2][2];
#pragma unroll
            for (int mi = 0; mi < 2; mi++) {
                const int r = wm + mi * 16 + g;
                a[mi][0] = __float_as_uint(as[r * LDP + kb + t4]);
                a[mi][1] = __float_as_uint(as[(r + 8) * LDP + kb + t4]);
                a[mi][2] = __float_as_uint(as[r * LDP + kb + t4 + 4]);
                a[mi][3] = __float_as_uint(as[(r + 8) * LDP + kb + t4 + 4]);
            }
#pragma unroll
            for (int ni = 0; ni < 2; ni++) {
                const int nn = wn + ni * 8 + g;
                b[ni][0] = __float_as_uint(bs[nn * LDP + kb + t4]);
                b[ni][1] = __float_as_uint(bs[nn * LDP + kb + t4 + 4]);
            }
#pragma unroll
            for (int mi = 0; mi < 2; mi++)
#pragma unroll
                for (int ni = 0; ni < 2; ni++)
                    mma_tf32(acc[mi][ni], a[mi], b[ni]);
        }
        __syncthreads();
        if (c + 2 < NC) load_chunk(s, c + 2);
    }

    // epilogue
#pragma unroll
    for (int mi = 0; mi < 2; mi++) {
        const int r0 = m0 + wm + mi * 16 + g;
        const int r1 = r0 + 8;
#pragma unroll
        for (int ni = 0; ni < 2; ni++) {
            const int cc = n0 + wn + ni * 8 + t4 * 2;
            float b0 = 0.f, b1 = 0.f;
            if (bias) {
                const float2 bb = *(const float2*)(bias + cc);
                b0 = bb.x; b1 = bb.y;
            }
            float i00 = 0.f, i01 = 0.f, i10 = 0.f, i11 = 0.f;
            if (Cinit) {
                const float2 c0r = *(const float2*)(Cinit + (size_t)r0 * ldc + cc);
                const float2 c1r = *(const float2*)(Cinit + (size_t)r1 * ldc + cc);
                i00 = c0r.x; i01 = c0r.y; i10 = c1r.x; i11 = c1r.y;
            }
            float2 o0, o1;
            o0.x = acc[mi][ni][0] + b0 + i00;
            o0.y = acc[mi][ni][1] + b1 + i01;
            o1.x = acc[mi][ni][2] + b0 + i10;
            o1.y = acc[mi][ni][3] + b1 + i11;
            *(float2*)(C + (size_t)r0 * ldc + cc) = o0;
            *(float2*)(C + (size_t)r1 * ldc + cc) = o1;
        }
    }
}

// ----------------------- dones dtype detect + decode -----------------------
__global__ __launch_bounds__(256) void dones_prep_k(const unsigned char* __restrict__ raw)
{
    __shared__ int f_anom, f_mis;
    const int b = threadIdx.x;
    if (b == 0) { f_anom = 0; f_mis = 0; }
    __syncthreads();
    unsigned char v = raw[b];
    if (v > 1) atomicOr(&f_anom, 1);
    if ((b & 3) != 0 && v == 1) atomicOr(&f_mis, 1);
    __syncthreads();
    unsigned char o;
    if (f_anom)      o = (raw[b * 4 + 3] != 0) ? 1 : 0;  // float32
    else if (f_mis)  o = v;                               // uint8/bool
    else             o = raw[b * 4];                      // int32 LSB
    g_dones[b] = o;
}

// --------------------------- fused GLU + LayerNorm -------------------------
template <int W, bool TRANS, bool ROUND>
__global__ __launch_bounds__(256) void gluln_k(
    const float* __restrict__ Z, const float* __restrict__ sc,
    const float* __restrict__ bi, float* __restrict__ out)
{
    __shared__ float g[W];
    __shared__ float red[16];
    const int b = blockIdx.x, tid = threadIdx.x;
    const float* z = Z + (size_t)b * (2 * W);
    float ls = 0.f, lq = 0.f;
    for (int i = tid; i < W; i += 256) {
        float a = z[i];
        float xx = z[i + W];
        float gv = a / (1.f + __expf(-xx));
        g[i] = gv; ls += gv; lq += gv * gv;
    }
#pragma unroll
    for (int o = 16; o; o >>= 1) {
        ls += __shfl_xor_sync(0xffffffffu, ls, o);
        lq += __shfl_xor_sync(0xffffffffu, lq, o);
    }
    if ((tid & 31) == 0) { red[tid >> 5] = ls; red[8 + (tid >> 5)] = lq; }
    __syncthreads();
    if (tid == 0) {
        float s = 0.f, q = 0.f;
        for (int w = 0; w < 8; w++) { s += red[w]; q += red[8 + w]; }
        red[0] = s; red[8] = q;
    }
    __syncthreads();
    const float mean = red[0] * (1.0f / W);
    const float var = red[8] * (1.0f / W) - mean * mean;
    const float rstd = rsqrtf(var + 1e-6f);
    for (int i = tid; i < W; i += 256) {
        float o = (g[i] - mean) * rstd * sc[i] + bi[i];
        if (ROUND) o = tf32r(o);
        if (TRANS) out[(size_t)i * B_ + b] = o;
        else       out[(size_t)b * W + i] = o;
    }
}

// --------------------------- transpose / prep kernels ----------------------
// tiled transpose with tf32 rounding: in[R][C] -> out[C][R]
__global__ void transpose_t(const float* __restrict__ in, float* __restrict__ out,
                            int R, int C)
{
    __shared__ float t[32][33];
    const int c0 = blockIdx.x * 32, r0 = blockIdx.y * 32;
    const int x = threadIdx.x, y = threadIdx.y;
#pragma unroll
    for (int j = 0; j < 32; j += 8)
        t[y + j][x] = in[(size_t)(r0 + y + j) * C + c0 + x];
    __syncthreads();
#pragma unroll
    for (int j = 0; j < 32; j += 8)
        out[(size_t)(c0 + y + j) * R + r0 + x] = tf32r(t[x][y + j]);
}

// simple transpose (fp32): in[R][C] -> out[C][R]
__global__ __launch_bounds__(256) void transpose_k(
    const float* __restrict__ in, float* __restrict__ out, int R, int C)
{
    const int o = blockIdx.x * 256 + threadIdx.x;
    if (o >= R * C) return;
    const int c = o / R, r = o - c * R;
    out[o] = __ldg(in + (size_t)r * C + c);
}

// elementwise tf32 round-copy
__global__ __launch_bounds__(256) void round_copy_k(
    const float* __restrict__ in, float* __restrict__ out, int n)
{
    const int i = blockIdx.x * 256 + threadIdx.x;
    if (i < n) out[i] = tf32r(in[i]);
}

// last0 -> g_lastT[b][d] (tf32)
__global__ __launch_bounds__(256) void last0T_k(
    const float* __restrict__ at_tr, const float* __restrict__ start_at)
{
    const int b = blockIdx.x, tid = threadIdx.x;
    const bool dn = g_dones[b] != 0;
    for (int d = tid; d < D_; d += 256)
        g_lastT[(size_t)b * D_ + d] = tf32r(
            dn ? __ldg(start_at + d * M_ + (M_ - 1))
               : __ldg(at_tr + ((size_t)b * D_ + d) * M_ + (M_ - 1)));
}

// ------------------------------ NLM kernel ---------------------------------
template <int IT>
__global__ __launch_bounds__(256) void nlm_k(
    const float* __restrict__ st_tr, const float* __restrict__ start_st,
    const float* __restrict__ b1, const float* __restrict__ b2,
    const float* __restrict__ T1p, const float* __restrict__ T2p)
{
    const int d = blockIdx.x, b = threadIdx.x;
    __shared__ __align__(16) float w1s[32][36];
    __shared__ float w2s[32];
    __shared__ float b1s[32];
    __shared__ float sts[32];
    __shared__ float b2s[2];

    const float* w1g = g_wt1 + (size_t)d * 1024;
    for (int i = b; i < 1024; i += 256) w1s[i >> 5][i & 31] = w1g[i];
    if (b < 32) {
        w2s[b] = g_wt2[d * 32 + b];
        b1s[b] = b1[d * 32 + b];
        sts[b] = start_st[d * 32 + b];
    }
    if (b < 2) b2s[b] = b2[d * 2 + b];
    __syncthreads();

    const float invT1 = 1.f / T1p[0], invT2 = 1.f / T2p[0];
    const bool dn = g_dones[b] != 0;
    const float* strow = st_tr + ((size_t)b * D_ + d) * M_;

    float sv[32];
#pragma unroll
    for (int m = 0; m < 32; m++) {
        if (m < 31 - IT) {
            const int mm = m + IT + 1;
            sv[m] = dn ? sts[mm] : __ldg(strow + mm);
        } else {
            sv[m] = g_h[(size_t)(m - (31 - IT)) * BD_ + (size_t)d * B_ + b];
        }
    }

    float y[32];
#pragma unroll
    for (int h = 0; h < 32; h++) y[h] = b1s[h];
#pragma unroll
    for (int m = 0; m < 32; m++) {
        const float s = sv[m];
#pragma unroll
        for (int h4 = 0; h4 < 8; h4++) {
            float4 w = *(const float4*)&w1s[m][h4 * 4];
            y[h4 * 4 + 0] += s * w.x; y[h4 * 4 + 1] += s * w.y;
            y[h4 * 4 + 2] += s * w.z; y[h4 * 4 + 3] += s * w.w;
        }
    }
    float gg[16];
#pragma unroll
    for (int h = 0; h < 16; h++) {
        const float a = y[h] * invT1;
        const float bb = y[h + 16] * invT1;
        gg[h] = a / (1.f + __expf(-bb));
    }
    float z0 = b2s[0], z1 = b2s[1];
#pragma unroll
    for (int h = 0; h < 16; h++) {
        z0 += gg[h] * w2s[h * 2];
        z1 += gg[h] * w2s[h * 2 + 1];
    }
    z0 *= invT2; z1 *= invT2;
    const float xo = z0 / (1.f + __expf(-z1));
    g_x[(size_t)IT * BD_ + (size_t)d * B_ + b] = xo;
    g_lastT[(size_t)b * D_ + d] = tf32r(xo);  // next iteration's GEMM A operand
}

// ------------------------------ final outputs ------------------------------
__global__ __launch_bounds__(256) void output_k(
    const float* __restrict__ st_tr, const float* __restrict__ at_tr,
    const float* __restrict__ start_st, const float* __restrict__ start_at,
    float* __restrict__ out)
{
    const int d = blockIdx.x, b = threadIdx.x;
    __shared__ float sst[32], sat[32];
    if (b < 32) { sst[b] = start_st[d * M_ + b]; sat[b] = start_at[d * M_ + b]; }
    __syncthreads();
    const bool dn = g_dones[b] != 0;
    const size_t base = ((size_t)b * D_ + d) * M_;

    float v[32];
#pragma unroll
    for (int m = 0; m < 28; m++) v[m] = dn ? sst[m + 4] : __ldg(st_tr + base + m + 4);
#pragma unroll
    for (int j = 0; j < 4; j++) v[28 + j] = g_h[(size_t)j * BD_ + (size_t)d * B_ + b];
    float* o = out + base;
#pragma unroll
    for (int q = 0; q < 8; q++)
        *(float4*)(o + q * 4) = make_float4(v[q*4], v[q*4+1], v[q*4+2], v[q*4+3]);

#pragma unroll
    for (int m = 0; m < 28; m++) v[m] = dn ? sat[m + 4] : __ldg(at_tr + base + m + 4);
#pragma unroll
    for (int j = 0; j < 4; j++) v[28 + j] = g_x[(size_t)j * BD_ + (size_t)d * B_ + b];
    o = out + (size_t)B_ * D_ * M_ + base;
#pragma unroll
    for (int q = 0; q < 8; q++)
        *(float4*)(o + q * 4) = make_float4(v[q*4], v[q*4+1], v[q*4+2], v[q*4+3]);
}

__global__ __launch_bounds__(256) void synch_k(
    const float* __restrict__ at_tr, const float* __restrict__ start_at,
    const float* __restrict__ dp, float* __restrict__ out)
{
    const int b = blockIdx.x, tid = threadIdx.x;
    __shared__ float S[32][65];
    const bool dn = g_dones[b] != 0;
    for (int idx = tid; idx < 32 * 64; idx += 256) {
        const int m = idx >> 6, j = idx & 63;
        const int d = D_ - NSY_ + j;
        float v;
        if (m < 28)
            v = dn ? __ldg(start_at + d * M_ + m + 4)
                   : __ldg(at_tr + ((size_t)b * D_ + d) * M_ + m + 4);
        else
            v = g_x[(size_t)(m - 28) * BD_ + (size_t)d * B_ + b];
        S[m][j] = v;
    }
    __syncthreads();
    for (int s = tid; s < SYNCH_; s += 256) {
        int i = (int)((129.0f - sqrtf(16641.0f - 8.0f * (float)s)) * 0.5f);
        if (i < 0) i = 0; if (i > 63) i = 63;
        while (i > 0 && i * (129 - i) / 2 > s) i--;
        while ((i + 1) * (129 - (i + 1)) / 2 <= s) i++;
        const int j = i + (s - i * (129 - i) / 2);
        const float c = fminf(fmaxf(dp[s], 0.f), 4.f);
        const float r = __expf(-c);
        float acc = 0.f, den = 0.f, p = 1.f;
#pragma unroll
        for (int m = 31; m >= 0; m--) {
            acc += p * S[m][i] * S[m][j];
            den += p;
            p *= r;
        }
        out[(size_t)b * SYNCH_ + s] = acc * rsqrtf(den);
    }
}

// ------------------------------- host driver -------------------------------
extern "C" void kernel_launch(void* const* d_in, const int* in_sizes, int n_in,
                              void* d_out, int out_size)
{
    const float* obs       = (const float*)d_in[0];
    const unsigned char* dones_raw = (const unsigned char*)d_in[1];
    const float* st_tr     = (const float*)d_in[3];
    const float* at_tr     = (const float*)d_in[4];
    const float* start_st  = (const float*)d_in[5];
    const float* start_at  = (const float*)d_in[6];
    const float* bb_w1     = (const float*)d_in[7];
    const float* bb_b1     = (const float*)d_in[8];
    const float* bb_ln1_s  = (const float*)d_in[9];
    const float* bb_ln1_b  = (const float*)d_in[10];
    const float* bb_w2     = (const float*)d_in[11];
    const float* bb_b2     = (const float*)d_in[12];
    const float* bb_ln2_s  = (const float*)d_in[13];
    const float* bb_ln2_b  = (const float*)d_in[14];
    const float* syn_w1    = (const float*)d_in[15];
    const float* syn_b1    = (const float*)d_in[16];
    const float* syn_ln1_s = (const float*)d_in[17];
    const float* syn_ln1_b = (const float*)d_in[18];
    const float* syn_w2    = (const float*)d_in[19];
    const float* syn_b2    = (const float*)d_in[20];
    const float* syn_ln2_s = (const float*)d_in[21];
    const float* syn_ln2_b = (const float*)d_in[22];
    const float* nlm1_w    = (const float*)d_in[23];
    const float* nlm1_b    = (const float*)d_in[24];
    const float* nlm1_T    = (const float*)d_in[25];
    const float* nlm2_w    = (const float*)d_in[26];
    const float* nlm2_b    = (const float*)d_in[27];
    const float* nlm2_T    = (const float*)d_in[28];
    const float* dp        = (const float*)d_in[29];
    float* out = (float*)d_out;

    float *z, *c1, *f1, *f, *h1, *h, *lastT, *obsr, *wt1, *wt2;
    float *WTbb1, *WTbb2, *WT1a, *WT1b, *WT2;
    cudaGetSymbolAddress((void**)&z,     g_z);
    cudaGetSymbolAddress((void**)&c1,    g_c1);
    cudaGetSymbolAddress((void**)&f1,    g_f1);
    cudaGetSymbolAddress((void**)&f,     g_f);
    cudaGetSymbolAddress((void**)&h1,    g_h1);
    cudaGetSymbolAddress((void**)&h,     g_h);
    cudaGetSymbolAddress((void**)&lastT, g_lastT);
    cudaGetSymbolAddress((void**)&obsr,  g_obsr);
    cudaGetSymbolAddress((void**)&wt1,   g_wt1);
    cudaGetSymbolAddress((void**)&wt2,   g_wt2);
    cudaGetSymbolAddress((void**)&WTbb1, g_WTbb1);
    cudaGetSymbolAddress((void**)&WTbb2, g_WTbb2);
    cudaGetSymbolAddress((void**)&WT1a,  g_WT1a);
    cudaGetSymbolAddress((void**)&WT1b,  g_WT1b);
    cudaGetSymbolAddress((void**)&WT2,   g_WT2);

    const dim3 thr(256);
    const dim3 tb(32, 8);

    dones_prep_k<<<1, thr>>>(dones_raw);
    round_copy_k<<<(B_ * OBS_ + 255) / 256, thr>>>(obs, obsr, B_ * OBS_);

    // weight transposes -> [n][k] (tf32-rounded)
    transpose_t<<<dim3(1024/32, 256/32),  tb>>>(bb_w1, WTbb1, 256, 1024);
    transpose_t<<<dim3(1024/32, 512/32),  tb>>>(bb_w2, WTbb2, 512, 1024);
    transpose_t<<<dim3(2048/32, 512/32),  tb>>>(syn_w1, WT1a, 512, 2048);
    transpose_t<<<dim3(2048/32, 1024/32), tb>>>(syn_w1 + (size_t)512 * 2048, WT1b, 1024, 2048);
    transpose_t<<<dim3(2048/32, 1024/32), tb>>>(syn_w2, WT2, 1024, 2048);
    // NLM weight layouts (fp32)
    transpose_k<<<(D_ * 1024 + 255) / 256, thr>>>(nlm1_w, wt1, 1024, D_);
    transpose_k<<<(D_ * 32 + 255) / 256, thr>>>(nlm2_w, wt2, 32, D_);

    // backbone
    gemm_mma<<<dim3(16, 4), thr>>>(obsr, WTbb1, bb_b1, nullptr, z, 256, 1024);
    gluln_k<512, false, true><<<B_, thr>>>(z, bb_ln1_s, bb_ln1_b, f1);
    gemm_mma<<<dim3(16, 4), thr>>>(f1, WTbb2, bb_b2, nullptr, z, 512, 1024);
    gluln_k<512, false, true><<<B_, thr>>>(z, bb_ln2_s, bb_ln2_b, f);

    // loop-invariant synapse part: c1 = f @ syn_w1[0:512] + syn_b1
    gemm_mma<<<dim3(32, 4), thr>>>(f, WT1a, syn_b1, nullptr, c1, 512, 2048);

    last0T_k<<<B_, thr>>>(at_tr, start_at);

    for (int t = 0; t < 4; t++) {
        gemm_mma<<<dim3(32, 4), thr>>>(lastT, WT1b, nullptr, c1, z, 1024, 2048);
        gluln_k<1024, false, true><<<B_, thr>>>(z, syn_ln1_s, syn_ln1_b, h1);
        gemm_mma<<<dim3(32, 4), thr>>>(h1, WT2, syn_b2, nullptr, z, 1024, 2048);
        gluln_k<1024, true, false><<<B_, thr>>>(z, syn_ln2_s, syn_ln2_b, h + (size_t)t * BD_);
        switch (t) {
            case 0: nlm_k<0><<<D_, thr>>>(st_tr, start_st, nlm1_b, nlm2_b, nlm1_T, nlm2_T); break;
            case 1: nlm_k<1><<<D_, thr>>>(st_tr, start_st, nlm1_b, nlm2_b, nlm1_T, nlm2_T); break;
            case 2: nlm_k<2><<<D_, thr>>>(st_tr, start_st, nlm1_b, nlm2_b, nlm1_T, nlm2_T); break;
            case 3: nlm_k<3><<<D_, thr>>>(st_tr, start_st, nlm1_b, nlm2_b, nlm1_T, nlm2_T); break;
        }
    }

    output_k<<<D_, thr>>>(st_tr, at_tr, start_st, start_at, out);
    synch_k<<<B_, thr>>>(at_tr, start_at, dp, out + (size_t)2 * B_ * D_ * M_);
}

// round 12
// speedup vs baseline: 1.7071x; 1.0725x over previous
#include <cuda_runtime.h>
#include <cstdint>

// ---------------------------------------------------------------------------
// CTMCell: B=256, OBS=256, DIN=512, D=1024, M=32, HID=16, NSY=64, ITERS=4
// Outputs: st [B,D,M], at [B,D,M], synch [B,2080]  (fp32, concatenated)
// GEMMs: mma.sync m16n8k8 tf32, 4-stage cp.async pipeline, warp tile 32x32.
// ---------------------------------------------------------------------------

#define B_   256
#define OBS_ 256
#define DIN_ 512
#define D_   1024
#define M_   32
#define NSY_ 64
#define SYNCH_ 2080
#define BD_ (B_ * D_)   // 262144

// ------------------------- scratch (static device) -------------------------
__device__ float g_z[B_ * 2048];
__device__ float g_c1[B_ * 2048];
__device__ float g_f1[B_ * DIN_];
__device__ float g_f[B_ * DIN_];
__device__ float g_h1[B_ * D_];
__device__ float g_h[4 * BD_];        // new st columns, [t][d][b]  (fp32)
__device__ float g_x[4 * BD_];        // new at columns, [t][d][b]  (fp32)
__device__ float g_lastT[B_ * D_];    // "last" activations, [b][d], tf32-rounded
__device__ float g_obsr[B_ * OBS_];   // obs, tf32-rounded
__device__ float g_wt1[D_ * 32 * 32];
__device__ float g_wt2[D_ * 32];
__device__ unsigned char g_dones[B_];
// transposed weights -> [n][k], k contiguous, tf32-rounded
__device__ float g_WTbb1[1024 * 256];
__device__ float g_WTbb2[1024 * 512];
__device__ float g_WT1a[2048 * 512];
__device__ float g_WT1b[2048 * 1024];
__device__ float g_WT2 [2048 * 1024];

// ------------------------------ helpers ------------------------------------
__device__ __forceinline__ float tf32r(float x) {
    uint32_t u;
    asm("cvt.rna.tf32.f32 %0, %1;" : "=r"(u) : "f"(x));
    return __uint_as_float(u);
}
__device__ __forceinline__ uint32_t smem_u32(const void* p) {
    uint32_t a;
    asm("{ .reg .u64 t; cvta.to.shared.u64 t, %1; cvt.u32.u64 %0, t; }"
        : "=r"(a) : "l"(p));
    return a;
}
#define CP_ASYNC16(dst, src) \
    asm volatile("cp.async.cg.shared.global [%0], [%1], 16;" \
                 :: "r"(dst), "l"(src) : "memory")
#define CP_COMMIT() asm volatile("cp.async.commit_group;" ::: "memory")

__device__ __forceinline__ void mma_tf32(float* c, const uint32_t* a, const uint32_t* b) {
    asm volatile(
        "mma.sync.aligned.m16n8k8.row.col.f32.tf32.tf32.f32 "
        "{%0,%1,%2,%3}, {%4,%5,%6,%7}, {%8,%9}, {%0,%1,%2,%3};"
        : "+f"(c[0]), "+f"(c[1]), "+f"(c[2]), "+f"(c[3])
        : "r"(a[0]), "r"(a[1]), "r"(a[2]), "r"(a[3]), "r"(b[0]), "r"(b[1]));
}

// ----------------------- tensor-core GEMM (tf32 mma.sync) ------------------
// C[M,N] = A[M,K](row-major) * Bt[N,K](row-major)^T (+bias[N]) (+Cinit[M,N])
// CTA 64x64, 4 warps (2m x 2n), warp tile 32x32, KC=32, 4-stage cp.async.
#define LDP 36                        // smem row pitch (floats)
#define STG_F (64 * LDP)              // floats per stage per matrix (2304)
#define NSTG 4
#define SMEM_GEMM (2 * NSTG * STG_F * 4)   // 73728 bytes

__global__ __launch_bounds__(128) void gemm_mma(
    const float* __restrict__ A, const float* __restrict__ Bt,
    const float* __restrict__ bias, const float* __restrict__ Cinit,
    float* __restrict__ C, int K, int ldc)
{
    extern __shared__ __align__(16) float dyn[];
    float* Asm = dyn;                     // [NSTG][STG_F]
    float* Bsm = dyn + NSTG * STG_F;      // [NSTG][STG_F]
    const int tid = threadIdx.x;
    const int m0 = blockIdx.y * 64, n0 = blockIdx.x * 64;
    const int w = tid >> 5, lane = tid & 31;
    const int wm = (w >> 1) * 32, wn = (w & 1) * 32;
    const int g = lane >> 2, t4 = lane & 3;
    const int NC = K / 32;

    float acc[2][4][4];
#pragma unroll
    for (int mi = 0; mi < 2; mi++)
#pragma unroll
        for (int ni = 0; ni < 4; ni++)
#pragma unroll
            for (int q = 0; q < 4; q++) acc[mi][ni][q] = 0.f;

    const uint32_t sa0 = smem_u32(Asm);
    const uint32_t sb0 = smem_u32(Bsm);

    auto load_chunk = [&](int s, int c) {
        const int k0 = c * 32;
#pragma unroll
        for (int i = 0; i < 4; i++) {
            const int gi = tid + i * 128;          // 0..511
            const int row = gi >> 3, g8 = gi & 7;  // row 0..63, 16B granule
            const uint32_t off = (uint32_t)s * (STG_F * 4) + (uint32_t)row * (LDP * 4) + (uint32_t)g8 * 16;
            CP_ASYNC16(sa0 + off, A  + (size_t)(m0 + row) * K + k0 + g8 * 4);
            CP_ASYNC16(sb0 + off, Bt + (size_t)(n0 + row) * K + k0 + g8 * 4);
        }
        CP_COMMIT();
    };

    load_chunk(0, 0);
    load_chunk(1, 1);
    load_chunk(2, 2);

    for (int c = 0; c < NC; c++) {
        const int s = c & 3;
        const int ahead = NC - 1 - c;
        if (ahead >= 2)      asm volatile("cp.async.wait_group 2;" ::: "memory");
        else if (ahead == 1) asm volatile("cp.async.wait_group 1;" ::: "memory");
        else                 asm volatile("cp.async.wait_group 0;" ::: "memory");
        __syncthreads();

        const float* as = Asm + s * STG_F;
        const float* bs = Bsm + s * STG_F;
#pragma unroll
        for (int kk = 0; kk < 4; kk++) {
            const int kb = kk * 8;
            uint32_t a[2][4], b[4][2];
#pragma unroll
            for (int mi = 0; mi < 2; mi++) {
                const int r = wm + mi * 16 + g;
                a[mi][0] = __float_as_uint(as[r * LDP + kb + t4]);
                a[mi][1] = __float_as_uint(as[(r + 8) * LDP + kb + t4]);
                a[mi][2] = __float_as_uint(as[r * LDP + kb + t4 + 4]);
                a[mi][3] = __float_as_uint(as[(r + 8) * LDP + kb + t4 + 4]);
            }
#pragma unroll
            for (int ni = 0; ni < 4; ni++) {
                const int nn = wn + ni * 8 + g;
                b[ni][0] = __float_as_uint(bs[nn * LDP + kb + t4]);
                b[ni][1] = __float_as_uint(bs[nn * LDP + kb + t4 + 4]);
            }
#pragma unroll
            for (int mi = 0; mi < 2; mi++)
#pragma unroll
                for (int ni = 0; ni < 4; ni++)
                    mma_tf32(acc[mi][ni], a[mi], b[ni]);
        }
        __syncthreads();
        if (c + 3 < NC) load_chunk((c + 3) & 3, c + 3);
    }

    // epilogue
#pragma unroll
    for (int mi = 0; mi < 2; mi++) {
        const int r0 = m0 + wm + mi * 16 + g;
        const int r1 = r0 + 8;
#pragma unroll
        for (int ni = 0; ni < 4; ni++) {
            const int cc = n0 + wn + ni * 8 + t4 * 2;
            float b0 = 0.f, b1 = 0.f;
            if (bias) {
                const float2 bb = *(const float2*)(bias + cc);
                b0 = bb.x; b1 = bb.y;
            }
            float i00 = 0.f, i01 = 0.f, i10 = 0.f, i11 = 0.f;
            if (Cinit) {
                const float2 c0r = *(const float2*)(Cinit + (size_t)r0 * ldc + cc);
                const float2 c1r = *(const float2*)(Cinit + (size_t)r1 * ldc + cc);
                i00 = c0r.x; i01 = c0r.y; i10 = c1r.x; i11 = c1r.y;
            }
            float2 o0, o1;
            o0.x = acc[mi][ni][0] + b0 + i00;
            o0.y = acc[mi][ni][1] + b1 + i01;
            o1.x = acc[mi][ni][2] + b0 + i10;
            o1.y = acc[mi][ni][3] + b1 + i11;
            *(float2*)(C + (size_t)r0 * ldc + cc) = o0;
            *(float2*)(C + (size_t)r1 * ldc + cc) = o1;
        }
    }
}

// ----------------------- dones dtype detect + decode -----------------------
__global__ __launch_bounds__(256) void dones_prep_k(const unsigned char* __restrict__ raw)
{
    __shared__ int f_anom, f_mis;
    const int b = threadIdx.x;
    if (b == 0) { f_anom = 0; f_mis = 0; }
    __syncthreads();
    unsigned char v = raw[b];
    if (v > 1) atomicOr(&f_anom, 1);
    if ((b & 3) != 0 && v == 1) atomicOr(&f_mis, 1);
    __syncthreads();
    unsigned char o;
    if (f_anom)      o = (raw[b * 4 + 3] != 0) ? 1 : 0;  // float32
    else if (f_mis)  o = v;                               // uint8/bool
    else             o = raw[b * 4];                      // int32 LSB
    g_dones[b] = o;
}

// --------------------------- fused GLU + LayerNorm -------------------------
template <int W, bool TRANS, bool ROUND>
__global__ __launch_bounds__(256) void gluln_k(
    const float* __restrict__ Z, const float* __restrict__ sc,
    const float* __restrict__ bi, float* __restrict__ out)
{
    __shared__ float g[W];
    __shared__ float red[16];
    const int b = blockIdx.x, tid = threadIdx.x;
    const float* z = Z + (size_t)b * (2 * W);
    float ls = 0.f, lq = 0.f;
    for (int i = tid; i < W; i += 256) {
        float a = z[i];
        float xx = z[i + W];
        float gv = a / (1.f + __expf(-xx));
        g[i] = gv; ls += gv; lq += gv * gv;
    }
#pragma unroll
    for (int o = 16; o; o >>= 1) {
        ls += __shfl_xor_sync(0xffffffffu, ls, o);
        lq += __shfl_xor_sync(0xffffffffu, lq, o);
    }
    if ((tid & 31) == 0) { red[tid >> 5] = ls; red[8 + (tid >> 5)] = lq; }
    __syncthreads();
    if (tid == 0) {
        float s = 0.f, q = 0.f;
        for (int w = 0; w < 8; w++) { s += red[w]; q += red[8 + w]; }
        red[0] = s; red[8] = q;
    }
    __syncthreads();
    const float mean = red[0] * (1.0f / W);
    const float var = red[8] * (1.0f / W) - mean * mean;
    const float rstd = rsqrtf(var + 1e-6f);
    for (int i = tid; i < W; i += 256) {
        float o = (g[i] - mean) * rstd * sc[i] + bi[i];
        if (ROUND) o = tf32r(o);
        if (TRANS) out[(size_t)i * B_ + b] = o;
        else       out[(size_t)b * W + i] = o;
    }
}

// --------------------------- transpose / prep kernels ----------------------
// all 5 weight transposes in one launch: in[R][C] -> out[C][R], tf32-rounded
__global__ void transpose_all(const float* __restrict__ w0, const float* __restrict__ w1,
                              const float* __restrict__ w2, const float* __restrict__ w3,
                              const float* __restrict__ w4)
{
    __shared__ float t[32][33];
    int R, C; const float* in; float* out;
    switch (blockIdx.y) {
        case 0:  R = 256;  C = 1024; in = w0; out = g_WTbb1; break;
        case 1:  R = 512;  C = 1024; in = w1; out = g_WTbb2; break;
        case 2:  R = 512;  C = 2048; in = w2; out = g_WT1a;  break;
        case 3:  R = 1024; C = 2048; in = w3; out = g_WT1b;  break;
        default: R = 1024; C = 2048; in = w4; out = g_WT2;   break;
    }
    const int tpr = C >> 5;
    const int nt = tpr * (R >> 5);
    const int tile = blockIdx.x;
    if (tile >= nt) return;
    const int c0 = (tile % tpr) * 32, r0 = (tile / tpr) * 32;
    const int x = threadIdx.x, y = threadIdx.y;
#pragma unroll
    for (int j = 0; j < 32; j += 8)
        t[y + j][x] = in[(size_t)(r0 + y + j) * C + c0 + x];
    __syncthreads();
#pragma unroll
    for (int j = 0; j < 32; j += 8)
        out[(size_t)(c0 + y + j) * R + r0 + x] = tf32r(t[x][y + j]);
}

// simple transpose (fp32): in[R][C] -> out[C][R]
__global__ __launch_bounds__(256) void transpose_k(
    const float* __restrict__ in, float* __restrict__ out, int R, int C)
{
    const int o = blockIdx.x * 256 + threadIdx.x;
    if (o >= R * C) return;
    const int c = o / R, r = o - c * R;
    out[o] = __ldg(in + (size_t)r * C + c);
}

// elementwise tf32 round-copy
__global__ __launch_bounds__(256) void round_copy_k(
    const float* __restrict__ in, float* __restrict__ out, int n)
{
    const int i = blockIdx.x * 256 + threadIdx.x;
    if (i < n) out[i] = tf32r(in[i]);
}

// last0 -> g_lastT[b][d] (tf32)
__global__ __launch_bounds__(256) void last0T_k(
    const float* __restrict__ at_tr, const float* __restrict__ start_at)
{
    const int b = blockIdx.x, tid = threadIdx.x;
    const bool dn = g_dones[b] != 0;
    for (int d = tid; d < D_; d += 256)
        g_lastT[(size_t)b * D_ + d] = tf32r(
            dn ? __ldg(start_at + d * M_ + (M_ - 1))
               : __ldg(at_tr + ((size_t)b * D_ + d) * M_ + (M_ - 1)));
}

// ------------------------------ NLM kernel ---------------------------------
template <int IT>
__global__ __launch_bounds__(256) void nlm_k(
    const float* __restrict__ st_tr, const float* __restrict__ start_st,
    const float* __restrict__ b1, const float* __restrict__ b2,
    const float* __restrict__ T1p, const float* __restrict__ T2p)
{
    const int d = blockIdx.x, b = threadIdx.x;
    __shared__ __align__(16) float w1s[32][36];
    __shared__ float w2s[32];
    __shared__ float b1s[32];
    __shared__ float sts[32];
    __shared__ float b2s[2];

    const float* w1g = g_wt1 + (size_t)d * 1024;
    for (int i = b; i < 1024; i += 256) w1s[i >> 5][i & 31] = w1g[i];
    if (b < 32) {
        w2s[b] = g_wt2[d * 32 + b];
        b1s[b] = b1[d * 32 + b];
        sts[b] = start_st[d * 32 + b];
    }
    if (b < 2) b2s[b] = b2[d * 2 + b];
    __syncthreads();

    const float invT1 = 1.f / T1p[0], invT2 = 1.f / T2p[0];
    const bool dn = g_dones[b] != 0;
    const float* strow = st_tr + ((size_t)b * D_ + d) * M_;

    float sv[32];
#pragma unroll
    for (int m = 0; m < 32; m++) {
        if (m < 31 - IT) {
            const int mm = m + IT + 1;
            sv[m] = dn ? sts[mm] : __ldg(strow + mm);
        } else {
            sv[m] = g_h[(size_t)(m - (31 - IT)) * BD_ + (size_t)d * B_ + b];
        }
    }

    float y[32];
#pragma unroll
    for (int h = 0; h < 32; h++) y[h] = b1s[h];
#pragma unroll
    for (int m = 0; m < 32; m++) {
        const float s = sv[m];
#pragma unroll
        for (int h4 = 0; h4 < 8; h4++) {
            float4 w = *(const float4*)&w1s[m][h4 * 4];
            y[h4 * 4 + 0] += s * w.x; y[h4 * 4 + 1] += s * w.y;
            y[h4 * 4 + 2] += s * w.z; y[h4 * 4 + 3] += s * w.w;
        }
    }
    float gg[16];
#pragma unroll
    for (int h = 0; h < 16; h++) {
        const float a = y[h] * invT1;
        const float bb = y[h + 16] * invT1;
        gg[h] = a / (1.f + __expf(-bb));
    }
    float z0 = b2s[0], z1 = b2s[1];
#pragma unroll
    for (int h = 0; h < 16; h++) {
        z0 += gg[h] * w2s[h * 2];
        z1 += gg[h] * w2s[h * 2 + 1];
    }
    z0 *= invT2; z1 *= invT2;
    const float xo = z0 / (1.f + __expf(-z1));
    g_x[(size_t)IT * BD_ + (size_t)d * B_ + b] = xo;
    g_lastT[(size_t)b * D_ + d] = tf32r(xo);  // next iteration's GEMM A operand
}

// ------------------------------ final outputs ------------------------------
__global__ __launch_bounds__(256) void output_k(
    const float* __restrict__ st_tr, const float* __restrict__ at_tr,
    const float* __restrict__ start_st, const float* __restrict__ start_at,
    float* __restrict__ out)
{
    const int d = blockIdx.x, b = threadIdx.x;
    __shared__ float sst[32], sat[32];
    if (b < 32) { sst[b] = start_st[d * M_ + b]; sat[b] = start_at[d * M_ + b]; }
    __syncthreads();
    const bool dn = g_dones[b] != 0;
    const size_t base = ((size_t)b * D_ + d) * M_;

    float v[32];
#pragma unroll
    for (int m = 0; m < 28; m++) v[m] = dn ? sst[m + 4] : __ldg(st_tr + base + m + 4);
#pragma unroll
    for (int j = 0; j < 4; j++) v[28 + j] = g_h[(size_t)j * BD_ + (size_t)d * B_ + b];
    float* o = out + base;
#pragma unroll
    for (int q = 0; q < 8; q++)
        *(float4*)(o + q * 4) = make_float4(v[q*4], v[q*4+1], v[q*4+2], v[q*4+3]);

#pragma unroll
    for (int m = 0; m < 28; m++) v[m] = dn ? sat[m + 4] : __ldg(at_tr + base + m + 4);
#pragma unroll
    for (int j = 0; j < 4; j++) v[28 + j] = g_x[(size_t)j * BD_ + (size_t)d * B_ + b];
    o = out + (size_t)B_ * D_ * M_ + base;
#pragma unroll
    for (int q = 0; q < 8; q++)
        *(float4*)(o + q * 4) = make_float4(v[q*4], v[q*4+1], v[q*4+2], v[q*4+3]);
}

__global__ __launch_bounds__(256) void synch_k(
    const float* __restrict__ at_tr, const float* __restrict__ start_at,
    const float* __restrict__ dp, float* __restrict__ out)
{
    const int b = blockIdx.x, tid = threadIdx.x;
    __shared__ float S[32][65];
    const bool dn = g_dones[b] != 0;
    for (int idx = tid; idx < 32 * 64; idx += 256) {
        const int m = idx >> 6, j = idx & 63;
        const int d = D_ - NSY_ + j;
        float v;
        if (m < 28)
            v = dn ? __ldg(start_at + d * M_ + m + 4)
                   : __ldg(at_tr + ((size_t)b * D_ + d) * M_ + m + 4);
        else
            v = g_x[(size_t)(m - 28) * BD_ + (size_t)d * B_ + b];
        S[m][j] = v;
    }
    __syncthreads();
    for (int s = tid; s < SYNCH_; s += 256) {
        int i = (int)((129.0f - sqrtf(16641.0f - 8.0f * (float)s)) * 0.5f);
        if (i < 0) i = 0; if (i > 63) i = 63;
        while (i > 0 && i * (129 - i) / 2 > s) i--;
        while ((i + 1) * (129 - (i + 1)) / 2 <= s) i++;
        const int j = i + (s - i * (129 - i) / 2);
        const float c = fminf(fmaxf(dp[s], 0.f), 4.f);
        const float r = __expf(-c);
        float acc = 0.f, den = 0.f, p = 1.f;
#pragma unroll
        for (int m = 31; m >= 0; m--) {
            acc += p * S[m][i] * S[m][j];
            den += p;
            p *= r;
        }
        out[(size_t)b * SYNCH_ + s] = acc * rsqrtf(den);
    }
}

// ------------------------------- host driver -------------------------------
extern "C" void kernel_launch(void* const* d_in, const int* in_sizes, int n_in,
                              void* d_out, int out_size)
{
    const float* obs       = (const float*)d_in[0];
    const unsigned char* dones_raw = (const unsigned char*)d_in[1];
    const float* st_tr     = (const float*)d_in[3];
    const float* at_tr     = (const float*)d_in[4];
    const float* start_st  = (const float*)d_in[5];
    const float* start_at  = (const float*)d_in[6];
    const float* bb_w1     = (const float*)d_in[7];
    const float* bb_b1     = (const float*)d_in[8];
    const float* bb_ln1_s  = (const float*)d_in[9];
    const float* bb_ln1_b  = (const float*)d_in[10];
    const float* bb_w2     = (const float*)d_in[11];
    const float* bb_b2     = (const float*)d_in[12];
    const float* bb_ln2_s  = (const float*)d_in[13];
    const float* bb_ln2_b  = (const float*)d_in[14];
    const float* syn_w1    = (const float*)d_in[15];
    const float* syn_b1    = (const float*)d_in[16];
    const float* syn_ln1_s = (const float*)d_in[17];
    const float* syn_ln1_b = (const float*)d_in[18];
    const float* syn_w2    = (const float*)d_in[19];
    const float* syn_b2    = (const float*)d_in[20];
    const float* syn_ln2_s = (const float*)d_in[21];
    const float* syn_ln2_b = (const float*)d_in[22];
    const float* nlm1_w    = (const float*)d_in[23];
    const float* nlm1_b    = (const float*)d_in[24];
    const float* nlm1_T    = (const float*)d_in[25];
    const float* nlm2_w    = (const float*)d_in[26];
    const float* nlm2_b    = (const float*)d_in[27];
    const float* nlm2_T    = (const float*)d_in[28];
    const float* dp        = (const float*)d_in[29];
    float* out = (float*)d_out;

    float *z, *c1, *f1, *f, *h1, *h, *lastT, *obsr, *wt1, *wt2;
    float *WTbb1, *WTbb2, *WT1a, *WT1b, *WT2;
    cudaGetSymbolAddress((void**)&z,     g_z);
    cudaGetSymbolAddress((void**)&c1,    g_c1);
    cudaGetSymbolAddress((void**)&f1,    g_f1);
    cudaGetSymbolAddress((void**)&f,     g_f);
    cudaGetSymbolAddress((void**)&h1,    g_h1);
    cudaGetSymbolAddress((void**)&h,     g_h);
    cudaGetSymbolAddress((void**)&lastT, g_lastT);
    cudaGetSymbolAddress((void**)&obsr,  g_obsr);
    cudaGetSymbolAddress((void**)&wt1,   g_wt1);
    cudaGetSymbolAddress((void**)&wt2,   g_wt2);
    cudaGetSymbolAddress((void**)&WTbb1, g_WTbb1);
    cudaGetSymbolAddress((void**)&WTbb2, g_WTbb2);
    cudaGetSymbolAddress((void**)&WT1a,  g_WT1a);
    cudaGetSymbolAddress((void**)&WT1b,  g_WT1b);
    cudaGetSymbolAddress((void**)&WT2,   g_WT2);

    cudaFuncSetAttribute(gemm_mma, cudaFuncAttributeMaxDynamicSharedMemorySize, SMEM_GEMM);

    const dim3 thr(256);
    const dim3 thr128(128);
    const dim3 tb(32, 8);

    // 1..5: prep (ncu -s 5 -c 1 then catches launch 6 = first gemm_mma)
    dones_prep_k<<<1, thr>>>(dones_raw);
    round_copy_k<<<(B_ * OBS_ + 255) / 256, thr>>>(obs, obsr, B_ * OBS_);
    transpose_all<<<dim3(2048, 5), tb>>>(bb_w1, bb_w2, syn_w1,
                                         syn_w1 + (size_t)512 * 2048, syn_w2);
    transpose_k<<<(D_ * 1024 + 255) / 256, thr>>>(nlm1_w, wt1, 1024, D_);
    transpose_k<<<(D_ * 32 + 255) / 256, thr>>>(nlm2_w, wt2, 32, D_);

    // backbone
    gemm_mma<<<dim3(16, 4), thr128, SMEM_GEMM>>>(obsr, WTbb1, bb_b1, nullptr, z, 256, 1024);
    gluln_k<512, false, true><<<B_, thr>>>(z, bb_ln1_s, bb_ln1_b, f1);
    gemm_mma<<<dim3(16, 4), thr128, SMEM_GEMM>>>(f1, WTbb2, bb_b2, nullptr, z, 512, 1024);
    gluln_k<512, false, true><<<B_, thr>>>(z, bb_ln2_s, bb_ln2_b, f);

    // loop-invariant synapse part: c1 = f @ syn_w1[0:512] + syn_b1
    gemm_mma<<<dim3(32, 4), thr128, SMEM_GEMM>>>(f, WT1a, syn_b1, nullptr, c1, 512, 2048);

    last0T_k<<<B_, thr>>>(at_tr, start_at);

    for (int t = 0; t < 4; t++) {
        gemm_mma<<<dim3(32, 4), thr128, SMEM_GEMM>>>(lastT, WT1b, nullptr, c1, z, 1024, 2048);
        gluln_k<1024, false, true><<<B_, thr>>>(z, syn_ln1_s, syn_ln1_b, h1);
        gemm_mma<<<dim3(32, 4), thr128, SMEM_GEMM>>>(h1, WT2, syn_b2, nullptr, z, 1024, 2048);
        gluln_k<1024, true, false><<<B_, thr>>>(z, syn_ln2_s, syn_ln2_b, h + (size_t)t * BD_);
        switch (t) {
            case 0: nlm_k<0><<<D_, thr>>>(st_tr, start_st, nlm1_b, nlm2_b, nlm1_T, nlm2_T); break;
            case 1: nlm_k<1><<<D_, thr>>>(st_tr, start_st, nlm1_b, nlm2_b, nlm1_T, nlm2_T); break;
            case 2: nlm_k<2><<<D_, thr>>>(st_tr, start_st, nlm1_b, nlm2_b, nlm1_T, nlm2_T); break;
            case 3: nlm_k<3><<<D_, thr>>>(st_tr, start_st, nlm1_b, nlm2_b, nlm1_T, nlm2_T); break;
        }
    }

    output_k<<<D_, thr>>>(st_tr, at_tr, start_st, start_at, out);
    synch_k<<<B_, thr>>>(at_tr, start_at, dp, out + (size_t)2 * B_ * D_ * M_);
}